// round 7
// baseline (speedup 1.0000x reference)
#include <cuda_runtime.h>
#include <math.h>

#define N_NODES 20000
#define N_EDGES 320000

// ---------------- scratch (device globals) ----------------
// g_sv per node: s[0:64], v planar: 64 + 64*i + u   (i=0..2)
__device__ float g_sv[N_NODES * 256];
// g_agg per node: A[0:64], D[64:128], B planes 128+64*i+u, C planes 320+64*i+u
__device__ float g_agg[N_NODES * 512];
__device__ float g_gate[N_NODES * 64];

__device__ __forceinline__ float silu_n(float x) {
    return 1.679177f * x * (1.0f / (1.0f + __expf(-x)));
}

// ---------------- f32x2 packed-FMA helpers (Blackwell FFMA2) ----------------
typedef unsigned long long u64t;
__device__ __forceinline__ u64t pk2(float lo, float hi) {
    u64t r; asm("mov.b64 %0, {%1, %2};" : "=l"(r) : "f"(lo), "f"(hi)); return r;
}
__device__ __forceinline__ u64t pkdup(float v) {
    u64t r; asm("mov.b64 %0, {%1, %1};" : "=l"(r) : "f"(v)); return r;
}
__device__ __forceinline__ void fma2(u64t& d, u64t a, u64t b) {
    asm("fma.rn.f32x2 %0, %1, %2, %0;" : "+l"(d) : "l"(a), "l"(b));
}
__device__ __forceinline__ float2 up2(u64t v) {
    float2 r; asm("mov.b64 {%0, %1}, %2;" : "=f"(r.x), "=f"(r.y) : "l"(v)); return r;
}

// ---------------- K1: lin1, persistent blocks, weights staged in smem ----------------
__global__ void __launch_bounds__(256)
k1_lin1(const float* __restrict__ ns, const float* __restrict__ nv,
        const float* __restrict__ W1s, const float* __restrict__ W1v) {
    __shared__ float sWs[4096];
    __shared__ float sWv[4096];
    __shared__ float sIn[4][256];
    int tid = threadIdx.x;
    for (int i = tid; i < 4096; i += 256) {
        sWs[i] = W1s[i] * 0.125f;   // lin_norm folded
        sWv[i] = W1v[i] * 0.125f;
    }
    __syncthreads();
    int w = tid & 63, q = tid >> 6;
    const int ntile = N_NODES / 4;  // 5000

    for (int tile = blockIdx.x; tile < ntile; tile += gridDim.x) {
        int n0 = tile * 4;
        __syncthreads();
        for (int idx = tid; idx < 1024; idx += 256) {
            int q2 = idx >> 8, r = idx & 255;
            sIn[q2][r] = (r < 64) ? ns[(size_t)(n0 + q2) * 64 + r]
                                  : nv[(size_t)(n0 + q2) * 192 + (r - 64)];
        }
        __syncthreads();
        const float* si = sIn[q];
        float as = 0.f, a0 = 0.f, a1 = 0.f, a2 = 0.f;
#pragma unroll 4
        for (int u = 0; u < 64; u++) {
            float ws = sWs[u * 64 + w];
            float wv = sWv[u * 64 + w];
            as += si[u] * ws;
            a0 += si[64 + 3 * u + 0] * wv;
            a1 += si[64 + 3 * u + 1] * wv;
            a2 += si[64 + 3 * u + 2] * wv;
        }
        float* o = g_sv + (size_t)(n0 + q) * 256;
        o[w] = as;
        o[64 + w] = a0;
        o[128 + w] = a1;
        o[192 + w] = a2;
    }
}

// ---------------- K2: zero the aggregation buffer ----------------
__global__ void k2_zero() {
    int i = blockIdx.x * blockDim.x + threadIdx.x;
    int stride = gridDim.x * blockDim.x;
    float4* p = (float4*)g_agg;
    const int n4 = N_NODES * 512 / 4;
    for (; i < n4; i += stride) p[i] = make_float4(0.f, 0.f, 0.f, 0.f);
}

// ---------------- K3: fused edge MLP + scatter; 512 thr, 16 edges per warp-tile ----------------
// smem floats: sW0 512 + sW1T 64x66=4224 + sW2T 256x66=16896 + 16 warps * 1280 = 42112 -> 168448 B
#define K3_SMEM 168448
__global__ void __launch_bounds__(512, 1)
k3_edge(const float* __restrict__ esh, const float* __restrict__ emb,
        const int* __restrict__ esrc, const int* __restrict__ edst,
        const float* __restrict__ W0, const float* __restrict__ W1,
        const float* __restrict__ W2) {
    extern __shared__ float sm[];
    float* sW0  = sm;          // [8][64]   pre-scaled 1/sqrt(8)
    float* sW1T = sm + 512;    // [j=64][k stride 66] transposed, pre-scaled 0.125
    float* sW2T = sm + 4736;   // [c=256][k stride 66] transposed, pre-scaled 0.125
    int tid = threadIdx.x;
    for (int i = tid; i < 512; i += 512) sW0[i] = W0[i] * 0.35355339059327373f;
    for (int i = tid; i < 4096; i += 512) {
        int k = i >> 6, j = i & 63;
        sW1T[j * 66 + k] = W1[i] * 0.125f;   // W1[i] = W1[k*64+j]
    }
    for (int i = tid; i < 16384; i += 512) {
        int k = i >> 8, c = i & 255;
        sW2T[c * 66 + k] = W2[i] * 0.125f;   // W2[i] = W2[k*256+c]
    }
    __syncthreads();

    int warp = tid >> 5, lane = tid & 31;
    float* pHT = sm + 21632 + warp * 1280;  // [e=16][stride 66]: h0 then h1 in-place
    float* pEB = pHT + 1056;                // 128: emb for 16 edges
    float* pSH = pEB + 128;                 // 64: sh for 16 edges
    int*   pIX = (int*)(pSH + 64);          // 32: src[16], dst[16]

    const float inv_sqrt3 = 0.57735026918962576f;
    const int ntile = N_EDGES / 16;  // 20000
    int gw = blockIdx.x * 16 + warp;
    int gstride = gridDim.x * 16;

    for (int tile = gw; tile < ntile; tile += gstride) {
        int e0 = tile * 16;
        // ---- edge meta (coalesced) ----
        pIX[lane] = (lane < 16) ? __ldg(esrc + e0 + lane) : __ldg(edst + e0 + lane - 16);
#pragma unroll
        for (int i = 0; i < 4; i++)
            pEB[lane + 32 * i] = __ldg(emb + (size_t)e0 * 8 + lane + 32 * i);
        pSH[lane]      = __ldg(esh + (size_t)e0 * 4 + lane);
        pSH[lane + 32] = __ldg(esh + (size_t)e0 * 4 + 32 + lane);
        __syncwarp();

        // ---- fc0: h0[e][j], lane computes j = lane, lane+32 ----
#pragma unroll
        for (int e = 0; e < 16; e++) {
            float eb[8];
#pragma unroll
            for (int b = 0; b < 8; b++) eb[b] = pEB[e * 8 + b];
#pragma unroll
            for (int jj = 0; jj < 2; jj++) {
                int j = lane + 32 * jj;
                float a = 0.f;
#pragma unroll
                for (int b = 0; b < 8; b++) a += eb[b] * sW0[b * 64 + j];
                pHT[e * 66 + j] = silu_n(a);
            }
        }
        __syncwarp();

        // ---- fc1: k-paired FFMA2, two passes of 8 edges ----
#pragma unroll
        for (int p = 0; p < 2; p++) {
            u64t acc1[2][8];
#pragma unroll
            for (int o = 0; o < 2; o++)
#pragma unroll
                for (int e = 0; e < 8; e++) acc1[o][e] = 0ull;
#pragma unroll 4
            for (int kp = 0; kp < 32; kp++) {
                u64t w0 = *(const u64t*)(sW1T + lane * 66 + 2 * kp);
                u64t w1 = *(const u64t*)(sW1T + (lane + 32) * 66 + 2 * kp);
#pragma unroll
                for (int e = 0; e < 8; e++) {
                    u64t hp = *(const u64t*)(pHT + (8 * p + e) * 66 + 2 * kp);
                    fma2(acc1[0][e], w0, hp);
                    fma2(acc1[1][e], w1, hp);
                }
            }
            __syncwarp();  // all reads of h0 rows 8p..8p+7 done before overwriting
#pragma unroll
            for (int o = 0; o < 2; o++)
#pragma unroll
                for (int e = 0; e < 8; e++) {
                    float2 v = up2(acc1[o][e]);
                    pHT[(8 * p + e) * 66 + lane + 32 * o] = silu_n(v.x + v.y);
                }
            __syncwarp();
        }

        // ---- fc2 (k-paired) + epilogue: 4 groups of 4 edges ----
#pragma unroll
        for (int g = 0; g < 4; g++) {
            u64t acc[8][4];
#pragma unroll
            for (int c = 0; c < 8; c++)
#pragma unroll
                for (int e = 0; e < 4; e++) acc[c][e] = 0ull;
#pragma unroll 2
            for (int kp = 0; kp < 32; kp++) {
                u64t wd[8];
#pragma unroll
                for (int c = 0; c < 8; c++)
                    wd[c] = *(const u64t*)(sW2T + (lane + 32 * c) * 66 + 2 * kp);
#pragma unroll
                for (int e = 0; e < 4; e++) {
                    u64t hp = *(const u64t*)(pHT + (4 * g + e) * 66 + 2 * kp);
#pragma unroll
                    for (int c = 0; c < 8; c++) fma2(acc[c][e], wd[c], hp);
                }
            }
            // epilogue: per edge gather + coalesced atomic scatter
#pragma unroll
            for (int e = 0; e < 4; e++) {
                int ee = 4 * g + e;
                int src = pIX[ee], dst = pIX[16 + ee];
                src = min(max(src, 0), N_NODES - 1);
                dst = min(max(dst, 0), N_NODES - 1);
                float y0 = pSH[4 * ee + 0], Y1 = pSH[4 * ee + 1];
                float Y2 = pSH[4 * ee + 2], Y3 = pSH[4 * ee + 3];
                const float* sv = g_sv + (size_t)src * 256;
                float* ag = g_agg + (size_t)dst * 512;
#pragma unroll
                for (int half = 0; half < 2; half++) {
                    int u = lane + 32 * half;
                    float2 pA = up2(acc[half][e]);     float wA = pA.x + pA.y;
                    float2 pB = up2(acc[half + 2][e]); float wB = pB.x + pB.y;
                    float2 pC = up2(acc[half + 4][e]); float wC = pC.x + pC.y;
                    float2 pD = up2(acc[half + 6][e]); float wD = pD.x + pD.y;
                    float sA = __ldg(sv + u);
                    float v0 = __ldg(sv + 64 + u);
                    float v1 = __ldg(sv + 128 + u);
                    float v2 = __ldg(sv + 192 + u);
                    atomicAdd(ag + u, wA * sA * y0);
                    atomicAdd(ag + 64 + u, wD * (v0 * Y1 + v1 * Y2 + v2 * Y3) * inv_sqrt3);
                    float bs = wB * sA;
                    atomicAdd(ag + 128 + u, bs * Y1);
                    atomicAdd(ag + 192 + u, bs * Y2);
                    atomicAdd(ag + 256 + u, bs * Y3);
                    float cy = wC * y0;
                    atomicAdd(ag + 320 + u, cy * v0);
                    atomicAdd(ag + 384 + u, cy * v1);
                    atomicAdd(ag + 448 + u, cy * v2);
                }
            }
        }
        __syncwarp();
    }
}

// ---------------- K4a: s_h = [agg_s | ns(x)attr] @ Wcat, gates + out_s ----------------
// smem: W 49152 + ops 384*16 = 55296 floats = 221184 B; 512 threads, 16 nodes/tile
#define K4A_SMEM 221184
__global__ void __launch_bounds__(512)
k4a(const float* __restrict__ ns, const float* __restrict__ attr,
    const float* __restrict__ Wl2s, const float* __restrict__ Wscs,
    float* __restrict__ out) {
    extern __shared__ float sm[];
    float* sW = sm;            // [384][128], pre-scaled
    float* sOp = sW + 49152;   // [384][16]
    int tid = threadIdx.x;
    const float lin2n = 0.08838834764831845f;  // 1/sqrt(128)
    const float scn = 0.0625f;                 // 1/sqrt(256)
    for (int i = tid; i < 16384; i += 512) sW[i] = Wl2s[i] * lin2n;
    for (int i = tid; i < 32768; i += 512) sW[16384 + i] = Wscs[i] * scn;
    __syncthreads();

    int w = tid & 127, nh = tid >> 7;  // nh 0..3, nodes nh*4..nh*4+3
    const int ntile = N_NODES / 16;    // 1250

    for (int tile = blockIdx.x; tile < ntile; tile += gridDim.x) {
        int n0 = tile * 16;
        {
            int k = tid & 127, q = tid >> 7;
#pragma unroll
            for (int nn = 0; nn < 4; nn++) {
                int node = q * 4 + nn;
                sOp[k * 16 + node] = g_agg[(size_t)(n0 + node) * 512 + k] * 0.0625f;
            }
            for (int idx = tid; idx < 4096; idx += 512) {
                int m = idx >> 4, node = idx & 15;
                sOp[(128 + m) * 16 + node] =
                    ns[(size_t)(n0 + node) * 64 + (m >> 2)] * attr[(size_t)(n0 + node) * 4 + (m & 3)];
            }
        }
        __syncthreads();

        u64t a01 = 0ull, a23 = 0ull;
#pragma unroll 4
        for (int k = 0; k < 384; k++) {
            u64t wd = pkdup(sW[k * 128 + w]);
            ulonglong2 op = *(const ulonglong2*)(sOp + k * 16 + nh * 4);
            fma2(a01, wd, op.x);
            fma2(a23, wd, op.y);
        }
        float2 r01 = up2(a01), r23 = up2(a23);
        float r[4] = {r01.x, r01.y, r23.x, r23.y};
#pragma unroll
        for (int j = 0; j < 4; j++) {
            int n = n0 + nh * 4 + j;
            float val = silu_n(r[j]);
            if (w < 64) out[(size_t)n * 256 + w] = val;
            else        g_gate[(size_t)n * 64 + (w - 64)] = val;
        }
        __syncthreads();
    }
}

// ---------------- K4b: v_h = [agg_v | nv(x)attr] @ Wvcat, gate + out_v ----------------
// smem: W 24576 + ops 384*8*4 = 36864 floats = 147456 B; 512 threads, 8 nodes/tile
#define K4B_SMEM 147456
__global__ void __launch_bounds__(512)
k4b(const float* __restrict__ nv, const float* __restrict__ attr,
    const float* __restrict__ Wl2v, const float* __restrict__ Wscv,
    float* __restrict__ out) {
    extern __shared__ float sm[];
    float* sW = sm;            // [384][64], pre-scaled
    float* sOp = sW + 24576;   // [384][8 nodes][4]
    int tid = threadIdx.x;
    const float lin2n = 0.08838834764831845f;
    const float scn = 0.0625f;
    for (int i = tid; i < 8192; i += 512)  sW[i] = Wl2v[i] * lin2n;
    for (int i = tid; i < 16384; i += 512) sW[8192 + i] = Wscv[i] * scn;
    __syncthreads();

    int w = tid & 63, node = tid >> 6;  // node 0..7
    const int ntile = N_NODES / 8;      // 2500

    for (int tile = blockIdx.x; tile < ntile; tile += gridDim.x) {
        int n0 = tile * 8;
        for (int idx = tid; idx < 3072; idx += 512) {
            int k = idx >> 3, nd = idx & 7;
            int n = n0 + nd;
            float o0, o1, o2;
            if (k < 128) {
                const float* p = g_agg + (size_t)n * 512 + ((k < 64) ? (128 + k) : (320 + k - 64));
                o0 = p[0] * 0.0625f; o1 = p[64] * 0.0625f; o2 = p[128] * 0.0625f;
            } else {
                int m = k - 128;
                int u = m >> 2, v = m & 3;
                float av = attr[(size_t)n * 4 + v];
                const float* p = nv + (size_t)n * 192 + u * 3;
                o0 = p[0] * av; o1 = p[1] * av; o2 = p[2] * av;
            }
            *(float4*)(sOp + idx * 4) = make_float4(o0, o1, o2, 0.f);
        }
        __syncthreads();

        u64t a01 = 0ull;
        float a2 = 0.f;
#pragma unroll 4
        for (int k = 0; k < 384; k++) {
            float wk = sW[k * 64 + w];
            u64t wd = pkdup(wk);
            ulonglong2 op = *(const ulonglong2*)(sOp + (k * 8 + node) * 4);
            fma2(a01, wd, op.x);
            float2 t = up2(op.y);
            a2 += wk * t.x;
        }
        int n = n0 + node;
        float gate = g_gate[(size_t)n * 64 + w];
        float2 r = up2(a01);
        float* o = out + (size_t)n * 256 + 64 + 3 * w;
        o[0] = gate * r.x; o[1] = gate * r.y; o[2] = gate * a2;
        __syncthreads();
    }
}

// ---------------- launch ----------------
extern "C" void kernel_launch(void* const* d_in, const int* in_sizes, int n_in,
                              void* d_out, int out_size) {
    const float* node_scalars  = (const float*)d_in[0];
    const float* node_vectors  = (const float*)d_in[1];
    const float* node_attr     = (const float*)d_in[2];
    const float* edge_sh       = (const float*)d_in[3];
    const float* edge_embedded = (const float*)d_in[4];
    const int*   edge_src      = (const int*)d_in[5];
    const int*   edge_dst      = (const int*)d_in[6];
    const float* W_lin1_s      = (const float*)d_in[7];
    const float* W_lin1_v      = (const float*)d_in[8];
    const float* W_fc0         = (const float*)d_in[9];
    const float* W_fc1         = (const float*)d_in[10];
    const float* W_fc2         = (const float*)d_in[11];
    const float* W_lin2_s      = (const float*)d_in[12];
    const float* W_lin2_v      = (const float*)d_in[13];
    const float* W_sc_s        = (const float*)d_in[14];
    const float* W_sc_v        = (const float*)d_in[15];
    float* out = (float*)d_out;

    cudaFuncSetAttribute(k3_edge, cudaFuncAttributeMaxDynamicSharedMemorySize, K3_SMEM);
    cudaFuncSetAttribute(k4a, cudaFuncAttributeMaxDynamicSharedMemorySize, K4A_SMEM);
    cudaFuncSetAttribute(k4b, cudaFuncAttributeMaxDynamicSharedMemorySize, K4B_SMEM);

    k1_lin1<<<148, 256>>>(node_scalars, node_vectors, W_lin1_s, W_lin1_v);
    k2_zero<<<1024, 256>>>();
    k3_edge<<<148, 512, K3_SMEM>>>(edge_sh, edge_embedded, edge_src, edge_dst,
                                   W_fc0, W_fc1, W_fc2);
    k4a<<<148, 512, K4A_SMEM>>>(node_scalars, node_attr, W_lin2_s, W_sc_s, out);
    k4b<<<148, 512, K4B_SMEM>>>(node_vectors, node_attr, W_lin2_v, W_sc_v, out);
}